// round 2
// baseline (speedup 1.0000x reference)
#include <cuda_runtime.h>
#include <cuda_bf16.h>

// x: [B=16, C=64, H=256, W=256] fp32; conv_w [1,2,7,7]; conv_b [1]
// out = x * sigmoid(conv7x7(concat(mean_c(x), max_c(x))) + b)
//
// Pipelined megakernel: launch i runs concurrently
//   reduce(batch i), conv(batch i-1), mul(batch i-2)
// All dependencies cross launch boundaries (stream-ordered). 18 launches.
// Batch plane = 16 MB -> stays in L2 between its reduce and its mul,
// so x is read from DRAM only once.

#define B 16
#define C 64
#define HW 65536           // 256*256
#define HWf4 16384         // HW/4
#define PLANE (C * HW)     // 2^22 elements (16 MB)

#define TW 32
#define TH 8

#define RED_BLKS  64       // 16384 float4 pixels / 256
#define CONV_BLKS 256      // (256/TW)*(256/TH) = 8*32
#define MUL_BLKS  4096     // PLANE/4/256
#define TOT_BLKS  (RED_BLKS + CONV_BLKS + MUL_BLKS)

__device__ float g_att[B * 2 * HW];   // [b][{avg,max}][h*256+w]
__device__ float g_s[B * HW];         // sigmoid(conv) plane

__global__ void k_step(const float* __restrict__ x,
                       const float* __restrict__ cw,
                       const float* __restrict__ cb,
                       float* __restrict__ out,
                       int br, int bc, int bm) {
    // conv smem (statically allocated for every block; ~5 KB, harmless)
    __shared__ float s_avg[TH + 6][TW + 8];
    __shared__ float s_max[TH + 6][TW + 8];
    __shared__ float s_w[98];
    __shared__ float s_b;

    int bx = blockIdx.x;
    int tid = threadIdx.x;

    if (bx < RED_BLKS) {
        // ---------------- reduce: channel mean+max for batch br -------------
        if (br < 0) return;
        int q4 = bx * 256 + tid;                          // [0, HWf4)
        const float4* xb = reinterpret_cast<const float4*>(x + (size_t)br * PLANE);

        float4 v = xb[q4];
        float sx = v.x, sy = v.y, sz = v.z, sw = v.w;
        float mx = v.x, my = v.y, mz = v.z, mw = v.w;
#pragma unroll 8
        for (int c = 1; c < C; c++) {
            float4 u = xb[(size_t)c * HWf4 + q4];
            sx += u.x; sy += u.y; sz += u.z; sw += u.w;
            mx = fmaxf(mx, u.x); my = fmaxf(my, u.y);
            mz = fmaxf(mz, u.z); mw = fmaxf(mw, u.w);
        }
        const float inv = 1.0f / 64.0f;
        float4* avg_out = reinterpret_cast<float4*>(g_att + (size_t)br * 2 * HW);
        float4* max_out = reinterpret_cast<float4*>(g_att + (size_t)br * 2 * HW + HW);
        avg_out[q4] = make_float4(sx * inv, sy * inv, sz * inv, sw * inv);
        max_out[q4] = make_float4(mx, my, mz, mw);

    } else if (bx < RED_BLKS + CONV_BLKS) {
        // ---------------- conv 7x7 + bias + sigmoid for batch bc ------------
        if (bc < 0) return;
        int idx = bx - RED_BLKS;                           // [0, 256)
        int w0 = (idx & 7) * TW;                           // 8 tiles in w
        int h0 = (idx >> 3) * TH;                          // 32 tiles in h

        if (tid < 98) s_w[tid] = cw[tid];
        if (tid == 0) s_b = cb[0];

        const float* avgp = g_att + (size_t)bc * 2 * HW;
        const float* maxp = avgp + HW;

        for (int i = tid; i < 14 * 38; i += 256) {
            int dy = i / 38, dx = i - dy * 38;
            int hh = h0 - 3 + dy, ww = w0 - 3 + dx;
            float a = 0.f, m = 0.f;
            if (hh >= 0 && hh < 256 && ww >= 0 && ww < 256) {
                int ii = hh * 256 + ww;
                a = avgp[ii];
                m = maxp[ii];
            }
            s_avg[dy][dx] = a;
            s_max[dy][dx] = m;
        }
        __syncthreads();

        int lx = tid & (TW - 1);
        int ly = tid >> 5;
        float acc = s_b;
#pragma unroll
        for (int kh = 0; kh < 7; kh++) {
#pragma unroll
            for (int kw = 0; kw < 7; kw++) {
                acc = fmaf(s_w[kh * 7 + kw],      s_avg[ly + kh][lx + kw], acc);
                acc = fmaf(s_w[49 + kh * 7 + kw], s_max[ly + kh][lx + kw], acc);
            }
        }
        float sg = 1.0f / (1.0f + __expf(-acc));
        g_s[(size_t)bc * HW + (h0 + ly) * 256 + (w0 + lx)] = sg;

    } else {
        // ---------------- mul: out = x * s for batch bm ---------------------
        if (bm < 0) return;
        int idx = bx - (RED_BLKS + CONV_BLKS);             // [0, 4096)
        int t = idx * 256 + tid;                           // [0, PLANE/4)
        int q4 = t & (HWf4 - 1);

        const float4* xb = reinterpret_cast<const float4*>(x + (size_t)bm * PLANE);
        float4* ob = reinterpret_cast<float4*>(out + (size_t)bm * PLANE);
        const float4* sb = reinterpret_cast<const float4*>(g_s + (size_t)bm * HW);

        float4 xv = __ldcs(xb + t);        // read-once; hopefully L2 hit from reduce
        float4 sv = sb[q4];                // s plane: L2-resident
        xv.x *= sv.x; xv.y *= sv.y; xv.z *= sv.z; xv.w *= sv.w;
        __stcs(ob + t, xv);                // evict-first: don't pollute L2
    }
}

extern "C" void kernel_launch(void* const* d_in, const int* in_sizes, int n_in,
                              void* d_out, int out_size) {
    const float* x  = (const float*)d_in[0];
    const float* cw = (const float*)d_in[1];
    const float* cb = (const float*)d_in[2];
    float* out = (float*)d_out;

    for (int i = 0; i < B + 2; i++) {
        int br = (i < B) ? i : -1;
        int bc = (i - 1 >= 0 && i - 1 < B) ? i - 1 : -1;
        int bm = (i - 2 >= 0 && i - 2 < B) ? i - 2 : -1;
        k_step<<<TOT_BLKS, 256>>>(x, cw, cb, out, br, bc, bm);
    }
}

// round 3
// speedup vs baseline: 2.2070x; 2.2070x over previous
#include <cuda_runtime.h>
#include <cuda_bf16.h>

// x: [B=16, C=64, H=256, W=256] fp32; conv_w [1,2,7,7]; conv_b [1]
// out = x * sigmoid(conv7x7(concat(mean_c(x), max_c(x))) + b)
//
// Pipelined megakernel, 18 launches; launch i runs concurrently:
//   reduce(batch i), conv(batch i-1), mul(batch i-2)
// Batch plane = 16 MB stays in L2 between its reduce and its mul, so x is
// read from DRAM only once. Reduce is split 8 threads/pixel x 8 channels
// -> 512 CTAs/batch so it cannot straggle the launch.

#define B 16
#define C 64
#define HW 65536           // 256*256
#define HWf4 16384         // HW/4
#define PLANE (C * HW)     // 2^22 elements (16 MB)

#define TW 32
#define TH 8

#define RED_BLKS  512      // 16384 f4-pixels / 32 per block
#define CONV_BLKS 256
#define MUL_BLKS  4096
#define TOT_BLKS  (RED_BLKS + CONV_BLKS + MUL_BLKS)

__device__ float g_att[B * 2 * HW];   // [b][{avg,max}][h*256+w]
__device__ float g_s[B * HW];

__device__ __forceinline__ void f4add(float4& a, const float4 b) {
    a.x += b.x; a.y += b.y; a.z += b.z; a.w += b.w;
}
__device__ __forceinline__ void f4max(float4& a, const float4 b) {
    a.x = fmaxf(a.x, b.x); a.y = fmaxf(a.y, b.y);
    a.z = fmaxf(a.z, b.z); a.w = fmaxf(a.w, b.w);
}

__global__ void k_step(const float* __restrict__ x,
                       const float* __restrict__ cw,
                       const float* __restrict__ cb,
                       float* __restrict__ out,
                       int br, int bc, int bm) {
    __shared__ __align__(16) char sbuf[8704];   // shared by all roles

    int bx = blockIdx.x;
    int tid = threadIdx.x;

    if (bx < RED_BLKS) {
        // -------- reduce: mean+max over C for batch br (32 f4-pixels/blk) ---
        if (br < 0) return;
        int p = tid & 31;          // pixel within block
        int g = tid >> 5;          // channel group 0..7 (8 channels each)
        int q4 = bx * 32 + p;      // [0, HWf4)

        const float4* xb = reinterpret_cast<const float4*>(x + (size_t)br * PLANE);
        int c0 = g * 8;

        float4 sum = xb[(size_t)c0 * HWf4 + q4];
        float4 mx  = sum;
#pragma unroll
        for (int c = 1; c < 8; c++) {
            float4 u = xb[(size_t)(c0 + c) * HWf4 + q4];
            f4add(sum, u);
            f4max(mx, u);
        }

        float4* ssum = reinterpret_cast<float4*>(sbuf);        // [8][32]
        float4* smax = ssum + 256;                             // [8][32]
        ssum[g * 32 + p] = sum;
        smax[g * 32 + p] = mx;
        __syncthreads();

        if (g == 0) {
            float4 s = ssum[p];
            float4 m = smax[p];
#pragma unroll
            for (int gg = 1; gg < 8; gg++) {
                f4add(s, ssum[gg * 32 + p]);
                f4max(m, smax[gg * 32 + p]);
            }
            const float inv = 1.0f / 64.0f;
            float4* avg_out = reinterpret_cast<float4*>(g_att + (size_t)br * 2 * HW);
            float4* max_out = reinterpret_cast<float4*>(g_att + (size_t)br * 2 * HW + HW);
            avg_out[q4] = make_float4(s.x * inv, s.y * inv, s.z * inv, s.w * inv);
            max_out[q4] = m;
        }

    } else if (bx < RED_BLKS + CONV_BLKS) {
        // -------- conv 7x7 + bias + sigmoid for batch bc --------------------
        if (bc < 0) return;
        int idx = bx - RED_BLKS;                 // [0, 256)
        int w0 = (idx & 7) * TW;
        int h0 = (idx >> 3) * TH;

        float* s_avg = reinterpret_cast<float*>(sbuf);          // [14][40]
        float* s_max = s_avg + 14 * 40;                         // [14][40]
        float* s_w   = s_max + 14 * 40;                         // [98]
        float* s_b   = s_w + 98;                                // [1]

        if (tid < 98) s_w[tid] = cw[tid];
        if (tid == 0) s_b[0] = cb[0];

        const float* avgp = g_att + (size_t)bc * 2 * HW;
        const float* maxp = avgp + HW;

        for (int i = tid; i < 14 * 38; i += 256) {
            int dy = i / 38, dx = i - dy * 38;
            int hh = h0 - 3 + dy, ww = w0 - 3 + dx;
            float a = 0.f, m = 0.f;
            if (hh >= 0 && hh < 256 && ww >= 0 && ww < 256) {
                int ii = hh * 256 + ww;
                a = avgp[ii];
                m = maxp[ii];
            }
            s_avg[dy * 40 + dx] = a;
            s_max[dy * 40 + dx] = m;
        }
        __syncthreads();

        int lx = tid & (TW - 1);
        int ly = tid >> 5;
        float acc = s_b[0];
#pragma unroll
        for (int kh = 0; kh < 7; kh++) {
#pragma unroll
            for (int kw = 0; kw < 7; kw++) {
                acc = fmaf(s_w[kh * 7 + kw],      s_avg[(ly + kh) * 40 + lx + kw], acc);
                acc = fmaf(s_w[49 + kh * 7 + kw], s_max[(ly + kh) * 40 + lx + kw], acc);
            }
        }
        float sg = 1.0f / (1.0f + __expf(-acc));
        g_s[(size_t)bc * HW + (h0 + ly) * 256 + (w0 + lx)] = sg;

    } else {
        // -------- mul: out = x * s for batch bm (x from L2) -----------------
        if (bm < 0) return;
        int idx = bx - (RED_BLKS + CONV_BLKS);   // [0, 4096)
        int t = idx * 256 + tid;                 // [0, PLANE/4)
        int q4 = t & (HWf4 - 1);

        const float4* xb = reinterpret_cast<const float4*>(x + (size_t)bm * PLANE);
        float4* ob = reinterpret_cast<float4*>(out + (size_t)bm * PLANE);
        const float4* sb = reinterpret_cast<const float4*>(g_s + (size_t)bm * HW);

        float4 xv = __ldcs(xb + t);
        float4 sv = sb[q4];
        xv.x *= sv.x; xv.y *= sv.y; xv.z *= sv.z; xv.w *= sv.w;
        __stcs(ob + t, xv);
    }
}

extern "C" void kernel_launch(void* const* d_in, const int* in_sizes, int n_in,
                              void* d_out, int out_size) {
    const float* x  = (const float*)d_in[0];
    const float* cw = (const float*)d_in[1];
    const float* cb = (const float*)d_in[2];
    float* out = (float*)d_out;

    for (int i = 0; i < B + 2; i++) {
        int br = (i < B) ? i : -1;
        int bc = (i - 1 >= 0 && i - 1 < B) ? i - 1 : -1;
        int bm = (i - 2 >= 0 && i - 2 < B) ? i - 2 : -1;
        k_step<<<TOT_BLKS, 256>>>(x, cw, cb, out, br, bc, bm);
    }
}